// round 9
// baseline (speedup 1.0000x reference)
#include <cuda_runtime.h>

#define NN 3072u
#define NPAIRS (NN * NN)                 // 9,437,184
#define TOTAL_QUADS (NPAIRS * 4u)        // 37,748,736 float4 slots
#define UNROLL 4u
#define TPB 256u
#define SPAN (TOTAL_QUADS / UNROLL)      // 9,437,184 quads per partition
#define PSTRIDE (SPAN / 4u)              // 2,359,296 pairs per partition step
#define ISTRIDE (PSTRIDE / NN)           // 768 rows per partition step (exact)
#define BSTRIDE (PSTRIDE / 8u)           // 294,912 mask bytes per step (exact)

// Bit-packed pair mask: 1 bit per pair, 1.2MB -> L2-resident for kernel B.
__device__ unsigned char g_bits[NPAIRS / 8u];

// node code: batch id if class valid, unique negative sentinel otherwise.
// jax x64 disabled: the "int64" inputs are actually int32.
__device__ __forceinline__ int node_code(int c, int b, unsigned idx) {
    bool ok = (c != 24) && (c != 25) && (c != 26);
    return ok ? b : (int)(-1 - (int)idx);
}

// Kernel A: stream seg once (38MB read), emit bit-packed mask (1.2MB).
// Thread t handles 8 consecutive pairs of one row (NN % 8 == 0).
__global__ void __launch_bounds__(TPB)
build_mask_kernel(const float4* __restrict__ seg4,
                  const int* __restrict__ cls,
                  const int* __restrict__ batch) {
    unsigned t  = blockIdx.x * TPB + threadIdx.x;    // < NPAIRS/8
    unsigned i  = t / (NN / 8u);
    unsigned j0 = (t - i * (NN / 8u)) * 8u;

    float4 s0 = __ldcs(seg4 + 2u * t);
    float4 s1 = __ldcs(seg4 + 2u * t + 1u);

    int ci = node_code(__ldg(cls + i), __ldg(batch + i), i);

    int4 cj0 = *reinterpret_cast<const int4*>(cls + j0);
    int4 cj1 = *reinterpret_cast<const int4*>(cls + j0 + 4u);
    int4 bj0 = *reinterpret_cast<const int4*>(batch + j0);
    int4 bj1 = *reinterpret_cast<const int4*>(batch + j0 + 4u);

    unsigned byte = 0u;
    byte |= (unsigned)((ci == node_code(cj0.x, bj0.x, j0 + 0u)) && (s0.x == 0.0f) && (i != j0 + 0u)) << 0;
    byte |= (unsigned)((ci == node_code(cj0.y, bj0.y, j0 + 1u)) && (s0.y == 0.0f) && (i != j0 + 1u)) << 1;
    byte |= (unsigned)((ci == node_code(cj0.z, bj0.z, j0 + 2u)) && (s0.z == 0.0f) && (i != j0 + 2u)) << 2;
    byte |= (unsigned)((ci == node_code(cj0.w, bj0.w, j0 + 3u)) && (s0.w == 0.0f) && (i != j0 + 3u)) << 3;
    byte |= (unsigned)((ci == node_code(cj1.x, bj1.x, j0 + 4u)) && (s1.x == 0.0f) && (i != j0 + 4u)) << 4;
    byte |= (unsigned)((ci == node_code(cj1.y, bj1.y, j0 + 5u)) && (s1.y == 0.0f) && (i != j0 + 5u)) << 5;
    byte |= (unsigned)((ci == node_code(cj1.z, bj1.z, j0 + 6u)) && (s1.z == 0.0f) && (i != j0 + 6u)) << 6;
    byte |= (unsigned)((ci == node_code(cj1.w, bj1.w, j0 + 7u)) && (s1.w == 0.0f) && (i != j0 + 7u)) << 7;

    g_bits[t] = (unsigned char)byte;     // L2-resident hand-off
}

// Kernel B: pure DRAM write stream. Partition algebra:
//   PSTRIDE = 768*NN exactly, and PSTRIDE % 8 == 0, SPAN % 4 == 0, so across
//   a thread's 4 partitions: q constant, j constant (-> single z2 load),
//   i = i0 + 768k (one div total), mask bit index constant (bytes stride).
__global__ void __launch_bounds__(TPB, 8)      // pin regs <=32 -> full occ
pair_write_kernel(const float4* __restrict__ z1,   // [N][4] float4
                  const float4* __restrict__ z2,   // [N][4] float4
                  float4* __restrict__ out)        // [N*N*4]
{
    unsigned base = blockIdx.x * TPB + threadIdx.x;   // < SPAN
    unsigned pr0  = base >> 2;
    unsigned q    = base & 3u;
    unsigned i0   = pr0 / NN;
    unsigned j    = pr0 - i0 * NN;
    unsigned bit  = pr0 & 7u;
    unsigned byt  = pr0 >> 3;

    // Front-batched mask loads (L2-hot, warp-uniform bytes), MLP=4.
    unsigned mb[UNROLL];
#pragma unroll
    for (unsigned k = 0; k < UNROLL; k++)
        mb[k] = (unsigned)g_bits[byt + k * BSTRIDE];

    float4 b = z2[j * 4u + q];           // shared by all 4 partitions
    float4 vdef = make_float4(q == 0u ? 1.0f : 0.0f, 0.0f, 0.0f, 0.0f);

#pragma unroll
    for (unsigned k = 0; k < UNROLL; k++) {
        float4 v = vdef;
        if ((mb[k] >> bit) & 1u) {
            float4 a = z1[(i0 + k * ISTRIDE) * 4u + q];  // cache-hot
            v = make_float4(a.x * b.x, a.y * b.y, a.z * b.z, a.w * b.w);
        }
        __stcs(out + base + k * SPAN, v);    // 604MB pure write stream
    }
}

extern "C" void kernel_launch(void* const* d_in, const int* in_sizes, int n_in,
                              void* d_out, int out_size) {
    const float4* z1    = (const float4*)d_in[0];
    const float4* z2    = (const float4*)d_in[1];
    const float4* seg4  = (const float4*)d_in[2];
    const int*    cls   = (const int*)d_in[3];
    const int*    batch = (const int*)d_in[4];
    float4*       out   = (float4*)d_out;

    build_mask_kernel<<<(NPAIRS / 8u) / TPB, TPB>>>(seg4, cls, batch);
    pair_write_kernel<<<SPAN / TPB, TPB>>>(z1, z2, out);
}

// round 11
// speedup vs baseline: 1.0151x; 1.0151x over previous
#include <cuda_runtime.h>

#define NN 3072u
#define NPAIRS (NN * NN)                 // 9,437,184
#define TOTAL_QUADS (NPAIRS * 4u)        // 37,748,736 float4 slots
#define UNROLL 4u
#define TPB 256u
#define SPAN (TOTAL_QUADS / UNROLL)      // 9,437,184 quads per partition
#define PSTRIDE (SPAN / 4u)              // 2,359,296 pairs per partition step
#define ISTRIDE (PSTRIDE / NN)           // 768 rows per partition step (exact)
#define BSTRIDE (PSTRIDE / 8u)           // 294,912 mask bytes per step (exact)
#define NBYTES (NPAIRS / 8u)             // 1,179,648 mask bytes
#define NF4 (NBYTES / 16u)               // 73,728 float4 of mask

// Bit-packed pair mask (1 bit/pair, 1.2MB, L2-resident for kernel B).
__device__ __align__(16) unsigned char g_bits[NBYTES];
__device__ int g_code[NN];
__device__ int g_lo[NN];
__device__ int g_hi[NN];

// jax x64 disabled: the "int64" inputs are actually int32.
__device__ __forceinline__ int node_code(int c, int b, int idx) {
    bool ok = (c != 24) && (c != 25) && (c != 26);
    return ok ? b : (-1 - idx);
}

// Prep: per-node code + batch-segment bounds (batch is SORTED), and zero the
// bit mask. 3072 threads; each also zeroes 24 float4 of g_bits.
__global__ void __launch_bounds__(TPB)
prep_kernel(const int* __restrict__ cls, const int* __restrict__ batch) {
    int i = blockIdx.x * TPB + threadIdx.x;   // < NN (grid sized exactly)
    int b = batch[i];
    g_code[i] = node_code(cls[i], b, i);

    // lower_bound(batch, b)
    int lo = 0, n = (int)NN;
    while (lo < n) { int m = (lo + n) >> 1; if (batch[m] < b) lo = m + 1; else n = m; }
    // upper_bound(batch, b)
    int hi = 0;  n = (int)NN;
    while (hi < n) { int m = (hi + n) >> 1; if (batch[m] <= b) hi = m + 1; else n = m; }
    g_lo[i] = lo;
    g_hi[i] = hi;

    // zero mask: 24 float4 per thread, coalesced stride NN
    float4 z = make_float4(0.f, 0.f, 0.f, 0.f);
    float4* p = reinterpret_cast<float4*>(g_bits);
    unsigned t = (unsigned)i;
#pragma unroll
    for (unsigned k = 0; k < NF4 / NN; k++)
        p[t + k * NN] = z;
}

// Mask: warp per row, touching ONLY mask bytes overlapping the row's batch
// segment (~2.3MB of seg read instead of 38MB). Bits for j outside the
// segment are 0 via the code compare, so partial bytes are exact; bytes
// never visited stay zero (batch mismatch -> bit is genuinely 0).
__global__ void __launch_bounds__(TPB)
mask_row_kernel(const float* __restrict__ seg) {
    unsigned i    = blockIdx.x * 8u + (threadIdx.x >> 5);   // row, grid=NN/8
    unsigned lane = threadIdx.x & 31u;

    int ci = g_code[i];
    if (ci < 0) return;                       // invalid node: row stays zero

    unsigned rowbase = i * NN;
    unsigned b0 = (rowbase + (unsigned)g_lo[i]) >> 3;
    unsigned b1 = (rowbase + (unsigned)g_hi[i] - 1u) >> 3;

    for (unsigned byte = b0 + lane; byte <= b1; byte += 32u) {
        unsigned j0 = (byte << 3) - rowbase;  // 8-aligned column start
        const float4* p = reinterpret_cast<const float4*>(seg) + (byte << 1);
        float4 s0 = __ldcs(p);
        float4 s1 = __ldcs(p + 1);
        float sv[8] = {s0.x, s0.y, s0.z, s0.w, s1.x, s1.y, s1.z, s1.w};

        unsigned v = 0u;
#pragma unroll
        for (unsigned t = 0; t < 8u; t++) {
            unsigned j = j0 + t;
            bool bit = (ci == g_code[j]) && (sv[t] == 0.0f) && (j != i);
            v |= (unsigned)bit << t;
        }
        g_bits[byte] = (unsigned char)v;
    }
}

// Kernel B (R9-proven): pure 604MB write stream. Partition algebra:
// across a thread's 4 partitions q and j are constant (one z2 load), i
// strides by 768, mask bit index constant.
__global__ void __launch_bounds__(TPB, 8)
pair_write_kernel(const float4* __restrict__ z1,
                  const float4* __restrict__ z2,
                  float4* __restrict__ out) {
    unsigned base = blockIdx.x * TPB + threadIdx.x;   // < SPAN
    unsigned pr0  = base >> 2;
    unsigned q    = base & 3u;
    unsigned i0   = pr0 / NN;
    unsigned j    = pr0 - i0 * NN;
    unsigned bit  = pr0 & 7u;
    unsigned byt  = pr0 >> 3;

    unsigned mb[UNROLL];
#pragma unroll
    for (unsigned k = 0; k < UNROLL; k++)
        mb[k] = (unsigned)g_bits[byt + k * BSTRIDE];   // L2-hot, warp-uniform

    float4 b = z2[j * 4u + q];
    float4 vdef = make_float4(q == 0u ? 1.0f : 0.0f, 0.0f, 0.0f, 0.0f);

#pragma unroll
    for (unsigned k = 0; k < UNROLL; k++) {
        float4 v = vdef;
        if ((mb[k] >> bit) & 1u) {
            float4 a = z1[(i0 + k * ISTRIDE) * 4u + q];
            v = make_float4(a.x * b.x, a.y * b.y, a.z * b.z, a.w * b.w);
        }
        __stcs(out + base + k * SPAN, v);
    }
}

extern "C" void kernel_launch(void* const* d_in, const int* in_sizes, int n_in,
                              void* d_out, int out_size) {
    const float4* z1    = (const float4*)d_in[0];
    const float4* z2    = (const float4*)d_in[1];
    const float*  seg   = (const float*)d_in[2];
    const int*    cls   = (const int*)d_in[3];
    const int*    batch = (const int*)d_in[4];
    float4*       out   = (float4*)d_out;

    prep_kernel<<<NN / TPB, TPB>>>(cls, batch);           // 12 blocks
    mask_row_kernel<<<NN / 8u, TPB>>>(seg);               // 384 blocks
    pair_write_kernel<<<SPAN / TPB, TPB>>>(z1, z2, out);  // 36864 blocks
}

// round 13
// speedup vs baseline: 1.0293x; 1.0140x over previous
#include <cuda_runtime.h>

#define NN 3072u
#define NPAIRS (NN * NN)                 // 9,437,184
#define TOTAL_QUADS (NPAIRS * 4u)        // 37,748,736 float4 slots
#define UNROLL 4u
#define TPB 256u
#define SPAN (TOTAL_QUADS / UNROLL)      // 9,437,184 quads per partition
#define PSTRIDE (SPAN / 4u)              // 2,359,296 pairs per partition step
#define ISTRIDE (PSTRIDE / NN)           // 768 rows per partition step (exact)
#define BSTRIDE (PSTRIDE / 8u)           // 294,912 mask bytes per step (exact)
#define NBYTES (NPAIRS / 8u)             // 1,179,648 mask bytes
#define ROW_BYTES (NN / 8u)              // 384 mask bytes per row
#define ROWS_PER_BLK 8u                  // one warp per row
#define BLK_MASK_BYTES (ROWS_PER_BLK * ROW_BYTES)   // 3072 B, block-exclusive

// Bit-packed pair mask (1 bit/pair, 1.2MB, L2-resident for kernel B).
__device__ __align__(16) unsigned char g_bits[NBYTES];

// jax x64 disabled: the "int64" inputs are actually int32.
__device__ __forceinline__ int node_code(int c, int b, int idx) {
    bool ok = (c != 24) && (c != 25) && (c != 26);
    return ok ? b : (-1 - idx);
}

// Fused mask kernel (replaces prep + mask): each block owns 8 rows.
//  1) zero this block's 3072 mask bytes (block-exclusive, NN%8==0)
//  2) per warp: row code + batch-segment bounds (binary search, L1-hot)
//  3) write mask bytes only where the row's batch segment overlaps
//     (~2.3MB of seg read instead of 38MB). Bits for j outside the segment
//     are 0 via the code compare, so whole-byte stores at edges are exact.
__global__ void __launch_bounds__(TPB)
mask_row_kernel(const float* __restrict__ seg,
                const int* __restrict__ cls,
                const int* __restrict__ batch) {
    unsigned tid  = threadIdx.x;
    unsigned i    = blockIdx.x * ROWS_PER_BLK + (tid >> 5);   // grid = NN/8
    unsigned lane = tid & 31u;

    // 1) zero own mask slice: 192 float4, one per thread (tid < 192)
    if (tid < BLK_MASK_BYTES / 16u) {
        reinterpret_cast<float4*>(g_bits + blockIdx.x * BLK_MASK_BYTES)[tid] =
            make_float4(0.f, 0.f, 0.f, 0.f);
    }
    __syncthreads();

    // 2) row code + segment bounds (warp-redundant; batch is 12KB, L1-hot)
    int bi = __ldg(batch + i);
    int ci = node_code(__ldg(cls + i), bi, (int)i);
    if (ci < 0) return;                       // invalid node: row stays zero

    int lo = 0, n = (int)NN;                  // lower_bound(batch, bi)
    while (lo < n) { int m = (lo + n) >> 1; if (__ldg(batch + m) < bi) lo = m + 1; else n = m; }
    int hi = lo;  n = (int)NN;                // upper_bound(batch, bi)
    while (hi < n) { int m = (hi + n) >> 1; if (__ldg(batch + m) <= bi) hi = m + 1; else n = m; }

    unsigned rowbase = i * NN;
    unsigned b0 = (rowbase + (unsigned)lo) >> 3;
    unsigned b1 = (rowbase + (unsigned)hi - 1u) >> 3;

    // 3) per visited byte: 8 seg floats + inline j-codes -> 1 mask byte
    for (unsigned byte = b0 + lane; byte <= b1; byte += 32u) {
        unsigned j0 = (byte << 3) - rowbase;  // 8-aligned column start
        const float4* p = reinterpret_cast<const float4*>(seg) + (byte << 1);
        float4 s0 = __ldcs(p);
        float4 s1 = __ldcs(p + 1);
        float sv[8] = {s0.x, s0.y, s0.z, s0.w, s1.x, s1.y, s1.z, s1.w};

        int4 cj0 = *reinterpret_cast<const int4*>(cls + j0);
        int4 cj1 = *reinterpret_cast<const int4*>(cls + j0 + 4u);
        int4 bj0 = *reinterpret_cast<const int4*>(batch + j0);
        int4 bj1 = *reinterpret_cast<const int4*>(batch + j0 + 4u);
        int cj[8] = {node_code(cj0.x, bj0.x, (int)j0 + 0), node_code(cj0.y, bj0.y, (int)j0 + 1),
                     node_code(cj0.z, bj0.z, (int)j0 + 2), node_code(cj0.w, bj0.w, (int)j0 + 3),
                     node_code(cj1.x, bj1.x, (int)j0 + 4), node_code(cj1.y, bj1.y, (int)j0 + 5),
                     node_code(cj1.z, bj1.z, (int)j0 + 6), node_code(cj1.w, bj1.w, (int)j0 + 7)};

        unsigned v = 0u;
#pragma unroll
        for (unsigned t = 0; t < 8u; t++) {
            unsigned j = j0 + t;
            bool bit = (ci == cj[t]) && (sv[t] == 0.0f) && (j != i);
            v |= (unsigned)bit << t;
        }
        g_bits[byte] = (unsigned char)v;
    }
}

// Kernel B (R9-proven): pure 604MB write stream. Partition algebra:
// across a thread's 4 partitions q and j are constant (one z2 load), i
// strides by 768, mask bit index constant.
__global__ void __launch_bounds__(TPB, 8)
pair_write_kernel(const float4* __restrict__ z1,
                  const float4* __restrict__ z2,
                  float4* __restrict__ out) {
    unsigned base = blockIdx.x * TPB + threadIdx.x;   // < SPAN
    unsigned pr0  = base >> 2;
    unsigned q    = base & 3u;
    unsigned i0   = pr0 / NN;
    unsigned j    = pr0 - i0 * NN;
    unsigned bit  = pr0 & 7u;
    unsigned byt  = pr0 >> 3;

    unsigned mb[UNROLL];
#pragma unroll
    for (unsigned k = 0; k < UNROLL; k++)
        mb[k] = (unsigned)g_bits[byt + k * BSTRIDE];   // L2-hot, warp-uniform

    float4 b = z2[j * 4u + q];
    float4 vdef = make_float4(q == 0u ? 1.0f : 0.0f, 0.0f, 0.0f, 0.0f);

#pragma unroll
    for (unsigned k = 0; k < UNROLL; k++) {
        float4 v = vdef;
        if ((mb[k] >> bit) & 1u) {
            float4 a = z1[(i0 + k * ISTRIDE) * 4u + q];
            v = make_float4(a.x * b.x, a.y * b.y, a.z * b.z, a.w * b.w);
        }
        __stcs(out + base + k * SPAN, v);
    }
}

extern "C" void kernel_launch(void* const* d_in, const int* in_sizes, int n_in,
                              void* d_out, int out_size) {
    const float4* z1    = (const float4*)d_in[0];
    const float4* z2    = (const float4*)d_in[1];
    const float*  seg   = (const float*)d_in[2];
    const int*    cls   = (const int*)d_in[3];
    const int*    batch = (const int*)d_in[4];
    float4*       out   = (float4*)d_out;

    mask_row_kernel<<<NN / ROWS_PER_BLK, TPB>>>(seg, cls, batch); // 384 blocks
    pair_write_kernel<<<SPAN / TPB, TPB>>>(z1, z2, out);          // 36864 blocks
}

// round 16
// speedup vs baseline: 1.0967x; 1.0654x over previous
#include <cuda_runtime.h>

#define NN 3072u
#define NPAIRS (NN * NN)                 // 9,437,184
#define TOTAL_QUADS (NPAIRS * 4u)        // 37,748,736 float4 slots
#define UNROLL 4u
#define TPB 256u
#define SPAN (TOTAL_QUADS / UNROLL)      // 9,437,184 quads per partition
#define PSTRIDE (SPAN / 4u)              // 2,359,296 pairs per partition step
#define ISTRIDE (PSTRIDE / NN)           // 768 rows per partition step (exact)

// jax x64 disabled: the "int64" inputs are actually int32.
__device__ __forceinline__ int node_code(int c, int b, int idx) {
    bool ok = (c != 24) && (c != 25) && (c != 26);
    return ok ? b : (-1 - idx);
}

// Single fused kernel: 604MB write stream with the pair predicate resolved
// inline. Partition algebra (PSTRIDE = 768*NN exactly): across a thread's 4
// partitions q and j are constant (one z2 load, one j-code), i strides by
// 768 and is warp-uniform (broadcast cls/batch loads, L1-hot, 24KB total).
// seg is ONLY read for code-matching pairs (~6%, clustered in diagonal
// batch blocks -> a warp's matching lanes read one contiguous 32B sector):
// ~2.4MB of reads against 604MB of writes, so no stream-turnaround cost.
__global__ void __launch_bounds__(TPB, 8)
fused_pair_kernel(const float4* __restrict__ z1,   // [N][4] float4
                  const float4* __restrict__ z2,   // [N][4] float4
                  const float*  __restrict__ seg,  // [N*N]
                  const int*    __restrict__ cls,
                  const int*    __restrict__ batch,
                  float4*       __restrict__ out)  // [N*N*4]
{
    unsigned base = blockIdx.x * TPB + threadIdx.x;   // < SPAN
    unsigned pr0  = base >> 2;
    unsigned q    = base & 3u;
    unsigned i0   = pr0 / NN;
    unsigned j    = pr0 - i0 * NN;

    int code_j = node_code(__ldg(cls + j), __ldg(batch + j), (int)j);

    float4 b    = z2[j * 4u + q];            // shared by all 4 partitions
    float4 vdef = make_float4(q == 0u ? 1.0f : 0.0f, 0.0f, 0.0f, 0.0f);

#pragma unroll
    for (unsigned k = 0; k < UNROLL; k++) {
        unsigned i = i0 + k * ISTRIDE;       // warp-uniform row
        int code_i = node_code(__ldg(cls + i), __ldg(batch + i), (int)i);

        float4 v = vdef;
        if ((code_i == code_j) && (i != j)) {
            // seg + eye: diagonal excluded above; read seg only when the
            // batch/class gate passes (~6% of pairs).
            float s = __ldg(seg + i * NN + j);
            if (s == 0.0f) {
                float4 a = z1[i * 4u + q];   // cache-hot (96KB)
                v = make_float4(a.x * b.x, a.y * b.y, a.z * b.z, a.w * b.w);
            }
        }
        __stcs(out + base + k * SPAN, v);    // 604MB pure write stream
    }
}

extern "C" void kernel_launch(void* const* d_in, const int* in_sizes, int n_in,
                              void* d_out, int out_size) {
    const float4* z1    = (const float4*)d_in[0];
    const float4* z2    = (const float4*)d_in[1];
    const float*  seg   = (const float*)d_in[2];
    const int*    cls   = (const int*)d_in[3];
    const int*    batch = (const int*)d_in[4];
    float4*       out   = (float4*)d_out;

    fused_pair_kernel<<<SPAN / TPB, TPB>>>(z1, z2, seg, cls, batch, out);
}